// round 7
// baseline (speedup 1.0000x reference)
#include <cuda_runtime.h>
#include <math.h>
#include <stdint.h>

#define DM   512
#define LSEQ 256
#define BB   2
#define HH   8
#define DK   64
#define BH   16
#define BL   512
#define NEG_BIG -1.0e30f
#define POS_BIG  1.0e30f

// ---------------- scratch (device globals; no allocations allowed) -----------
__device__ float g_actq[BL * DM];
__device__ float g_actk[BL * DM];
__device__ float g_actv[BL * DM];
__device__ float g_Q[BH * LSEQ * DK];
__device__ float g_K[BH * LSEQ * DK];
__device__ float g_V[BH * LSEQ * DK];
__device__ float g_ctx[BL * DM];

// ---------------- tf32 helpers ------------------------------------------------
__device__ __forceinline__ float tf32r(float x) {
    uint32_t u;
    asm("cvt.rna.tf32.f32 %0, %1;" : "=r"(u) : "f"(x));
    return __uint_as_float(u);
}
__device__ __forceinline__ void mma_tf32(float* d, const uint32_t* a, const uint32_t* b) {
    asm volatile(
        "mma.sync.aligned.m16n8k8.row.col.f32.tf32.tf32.f32 "
        "{%0,%1,%2,%3}, {%4,%5,%6,%7}, {%8,%9}, {%0,%1,%2,%3};"
        : "+f"(d[0]), "+f"(d[1]), "+f"(d[2]), "+f"(d[3])
        : "r"(a[0]), "r"(a[1]), "r"(a[2]), "r"(a[3]), "r"(b[0]), "r"(b[1]));
}

// ---------------- tensor-core GEMM: Y = X @ W^T -------------------------------
// 64x64 block tile, 128 threads (4 warps of 32x32), K=512 in chunks of 32.
// mode 0: proj (3 gemms), epilogue log1p(relu(y)) - lam -> g_act*  grid (8,8,3)
// mode 1: out GEMM,       plain store -> out                       grid (8,8,1)
__global__ __launch_bounds__(128) void k_gemm_tc(const float* __restrict__ Xin,
                                                 const float* __restrict__ W0,
                                                 const float* __restrict__ W1,
                                                 const float* __restrict__ W2,
                                                 const float* __restrict__ lam,
                                                 float* __restrict__ outp,
                                                 int mode)
{
    __shared__ float As[64][36];
    __shared__ float Bs[64][36];

    const int gemm = (mode == 0) ? (int)blockIdx.z : 0;
    const float* X = (mode == 0) ? Xin : g_ctx;
    const float* W = (gemm == 0) ? W0 : ((gemm == 1) ? W1 : W2);
    float* Y = (mode == 0) ? ((gemm == 0) ? g_actq : ((gemm == 1) ? g_actk : g_actv))
                           : outp;

    const int bm = blockIdx.y, bn = blockIdx.x;
    const int tid = threadIdx.x;
    const int wid = tid >> 5, lane = tid & 31;
    const int warp_m = wid & 1;         // 2 warps over M
    const int warp_n = wid >> 1;        // 2 warps over N
    const int r = lane >> 2, c = lane & 3;
    const int m0w = warp_m * 32;
    const int n0w = warp_n * 32;

    float acc[2][4][4];
#pragma unroll
    for (int mt = 0; mt < 2; mt++)
#pragma unroll
        for (int nt = 0; nt < 4; nt++)
#pragma unroll
            for (int e = 0; e < 4; e++) acc[mt][nt][e] = 0.0f;

    for (int kc = 0; kc < DM; kc += 32) {
        // load + tf32-round chunk: A 64x32, B 64x32
#pragma unroll
        for (int pass = 0; pass < 4; pass++) {
            const int idx = tid + pass * 128;      // 0..511
            const int row = idx >> 3, c4 = (idx & 7) * 4;
            const float4 a = *(const float4*)&X[(bm * 64 + row) * DM + kc + c4];
            *(float4*)&As[row][c4] = make_float4(tf32r(a.x), tf32r(a.y),
                                                 tf32r(a.z), tf32r(a.w));
            const float4 b = *(const float4*)&W[(bn * 64 + row) * DM + kc + c4];
            *(float4*)&Bs[row][c4] = make_float4(tf32r(b.x), tf32r(b.y),
                                                 tf32r(b.z), tf32r(b.w));
        }
        __syncthreads();

#pragma unroll
        for (int ks = 0; ks < 32; ks += 8) {
            uint32_t af[2][4];
#pragma unroll
            for (int mt = 0; mt < 2; mt++) {
                const int mb = m0w + mt * 16;
                af[mt][0] = __float_as_uint(As[mb + r][ks + c]);
                af[mt][1] = __float_as_uint(As[mb + r + 8][ks + c]);
                af[mt][2] = __float_as_uint(As[mb + r][ks + c + 4]);
                af[mt][3] = __float_as_uint(As[mb + r + 8][ks + c + 4]);
            }
            uint32_t bf[4][2];
#pragma unroll
            for (int nt = 0; nt < 4; nt++) {
                const int nb = n0w + nt * 8;
                bf[nt][0] = __float_as_uint(Bs[nb + r][ks + c]);
                bf[nt][1] = __float_as_uint(Bs[nb + r][ks + c + 4]);
            }
#pragma unroll
            for (int mt = 0; mt < 2; mt++)
#pragma unroll
                for (int nt = 0; nt < 4; nt++)
                    mma_tf32(acc[mt][nt], af[mt], bf[nt]);
        }
        __syncthreads();
    }

    // epilogue
#pragma unroll
    for (int mt = 0; mt < 2; mt++) {
        const int row0 = bm * 64 + m0w + mt * 16 + r;
#pragma unroll
        for (int nt = 0; nt < 4; nt++) {
            const int col = bn * 64 + n0w + nt * 8 + c * 2;
            float y0 = acc[mt][nt][0], y1 = acc[mt][nt][1];
            float y2 = acc[mt][nt][2], y3 = acc[mt][nt][3];
            if (mode == 0) {
                const float l0 = lam[col], l1 = lam[col + 1];
                y0 = log1pf(fmaxf(y0, 0.0f)) - l0;
                y1 = log1pf(fmaxf(y1, 0.0f)) - l1;
                y2 = log1pf(fmaxf(y2, 0.0f)) - l0;
                y3 = log1pf(fmaxf(y3, 0.0f)) - l1;
            }
            *(float2*)&Y[row0 * DM + col] = make_float2(y0, y1);
            *(float2*)&Y[(row0 + 8) * DM + col] = make_float2(y2, y3);
        }
    }
}

// ---------------- tropical linear ---------------------------------------------
// Q/K/V[bh,l,o] = max_i( act[b,l,h*64+i] + Wt[o,i] )
__global__ __launch_bounds__(256) void k_trop(const float* __restrict__ Wqt,
                                              const float* __restrict__ Wkt,
                                              const float* __restrict__ Wvt)
{
    __shared__ float Wts[64][65];   // transposed: Wts[i][o]
    __shared__ float ar[16][65];

    const int gemm = blockIdx.z;
    const float* Wt = (gemm == 0) ? Wqt : ((gemm == 1) ? Wkt : Wvt);
    const float* act = (gemm == 0) ? g_actq : ((gemm == 1) ? g_actk : g_actv);
    float* out = (gemm == 0) ? g_Q : ((gemm == 1) ? g_K : g_V);
    const int bh = blockIdx.y;
    const int b = bh >> 3, h = bh & 7;
    const int l0 = blockIdx.x * 16;
    const int tid = threadIdx.x;

    for (int idx = tid; idx < 64 * 64; idx += 256) {
        const int o = idx >> 6, i = idx & 63;
        Wts[i][o] = Wt[idx];
    }
    for (int idx = tid; idx < 16 * 64; idx += 256) {
        const int r = idx >> 6, i = idx & 63;
        ar[r][i] = act[(b * LSEQ + l0 + r) * DM + h * DK + i];
    }
    __syncthreads();

    const int o = tid & 63, rg = tid >> 6;
    float m[4] = {NEG_BIG, NEG_BIG, NEG_BIG, NEG_BIG};
#pragma unroll 8
    for (int i = 0; i < 64; i++) {
        const float wv = Wts[i][o];
#pragma unroll
        for (int rr = 0; rr < 4; rr++)
            m[rr] = fmaxf(m[rr], ar[rg * 4 + rr][i] + wv);
    }
#pragma unroll
    for (int rr = 0; rr < 4; rr++)
        out[(bh * LSEQ + l0 + rg * 4 + rr) * DK + o] = m[rr];
}

// ---------------- fused tropical attention ------------------------------------
// i-tile = 8 rows, grid (32, 16) = 512 blocks, 256 threads.
__global__ __launch_bounds__(256, 4) void k_attn(float* __restrict__ scores)
{
    __shared__ float Qs[8][68];
    __shared__ float Ks[64][68];
    __shared__ float Vs[64][68];
    __shared__ float Ss[64][9];

    const int bh = blockIdx.y;
    const int it = blockIdx.x;        // 0..31
    const int i0 = it * 8;
    const int b = bh >> 3, h = bh & 7;
    const int tid = threadIdx.x;
    const int lane = tid & 31;
    const int w  = tid >> 5;          // warp 0..7 = phase-B i row
    const int ii = tid & 7;           // phase-A i
    const int jg = tid >> 3;          // phase-A j-group (0..31), 2 j each

    if (tid < 128) {
        const int r = tid >> 4, dq = (tid & 15) * 4;
        *(float4*)&Qs[r][dq] = *(const float4*)&g_Q[(bh * LSEQ + i0 + r) * DK + dq];
    }

    float accE0 = NEG_BIG, accE1 = NEG_BIG;
    float accO0 = NEG_BIG, accO1 = NEG_BIG;

    for (int cch = 0; cch < 4; cch++) {
        const float4* Kp = (const float4*)(g_K + (bh * LSEQ + cch * 64) * DK);
        const float4* Vp = (const float4*)(g_V + (bh * LSEQ + cch * 64) * DK);
        for (int idx = tid; idx < 1024; idx += 256) {
            const int j = idx >> 4, dq = (idx & 15) * 4;
            *(float4*)&Ks[j][dq] = Kp[idx];
            *(float4*)&Vs[j][dq] = Vp[idx];
        }
        __syncthreads();

        // ---- phase A: scores for 2 j per thread ----
        {
            const int j0 = jg * 2;
            float mxa[2] = {NEG_BIG, NEG_BIG}, mxb[2] = {NEG_BIG, NEG_BIG};
            float mna[2] = {POS_BIG, POS_BIG}, mnb[2] = {POS_BIG, POS_BIG};
#pragma unroll
            for (int t = 0; t < 16; t++) {
                const float4 q4 = *(const float4*)&Qs[ii][t * 4];
#pragma unroll
                for (int jj = 0; jj < 2; jj++) {
                    const float4 k4 = *(const float4*)&Ks[j0 + jj][t * 4];
                    const float d0 = q4.x - k4.x;
                    const float d1 = q4.y - k4.y;
                    const float d2 = q4.z - k4.z;
                    const float d3 = q4.w - k4.w;
                    mxa[jj] = fmaxf(mxa[jj], d0); mna[jj] = fminf(mna[jj], d0);
                    mxb[jj] = fmaxf(mxb[jj], d1); mnb[jj] = fminf(mnb[jj], d1);
                    mxa[jj] = fmaxf(mxa[jj], d2); mna[jj] = fminf(mna[jj], d2);
                    mxb[jj] = fmaxf(mxb[jj], d3); mnb[jj] = fminf(mnb[jj], d3);
                }
            }
#pragma unroll
            for (int jj = 0; jj < 2; jj++) {
                const float sc = fminf(mna[jj], mnb[jj]) - fmaxf(mxa[jj], mxb[jj]);
                Ss[j0 + jj][ii] = sc;
                scores[(bh * LSEQ + i0 + ii) * LSEQ + cch * 64 + j0 + jj] = sc;
            }
        }
        __syncthreads();

        // ---- phase B: context (warp = i row, d across lanes, j serial) ----
#pragma unroll 4
        for (int j = 0; j < 64; j += 2) {
            const float sE = Ss[j][w];
            const float sO = Ss[j + 1][w];
            const float2 vE = *(const float2*)&Vs[j][lane * 2];
            const float2 vO = *(const float2*)&Vs[j + 1][lane * 2];
            accE0 = fmaxf(accE0, sE + vE.x);
            accE1 = fmaxf(accE1, sE + vE.y);
            accO0 = fmaxf(accO0, sO + vO.x);
            accO1 = fmaxf(accO1, sO + vO.y);
        }
        __syncthreads();
    }

    {
        const int l = i0 + w;
        float2 v;
        v.x = expm1f(fmaxf(accE0, accO0));
        v.y = expm1f(fmaxf(accE1, accO1));
        *(float2*)&g_ctx[(b * LSEQ + l) * DM + h * DK + lane * 2] = v;
    }
}

// ---------------- launch ------------------------------------------------------
extern "C" void kernel_launch(void* const* d_in, const int* in_sizes, int n_in,
                              void* d_out, int out_size)
{
    const float* x   = (const float*)d_in[0];
    const float* Wq  = (const float*)d_in[1];
    const float* Wk  = (const float*)d_in[2];
    const float* Wv  = (const float*)d_in[3];
    const float* Wo  = (const float*)d_in[4];
    const float* lam = (const float*)d_in[5];
    const float* Wqt = (const float*)d_in[6];
    const float* Wkt = (const float*)d_in[7];
    const float* Wvt = (const float*)d_in[8];
    float* out = (float*)d_out;
    float* scores = out + BL * DM;   // (output, attn_scores) flattened in order

    k_gemm_tc<<<dim3(8, 8, 3), 128>>>(x, Wq, Wk, Wv, lam, nullptr, 0);  // projections
    k_trop<<<dim3(16, 16, 3), 256>>>(Wqt, Wkt, Wvt);                    // tropical linears
    k_attn<<<dim3(32, 16), 256>>>(scores);                              // scores+context
    k_gemm_tc<<<dim3(8, 8, 1), 128>>>(nullptr, Wo, nullptr, nullptr,
                                      nullptr, out, 1);                 // output GEMM
}